// round 4
// baseline (speedup 1.0000x reference)
#include <cuda_runtime.h>
#include <cstdint>

// DCNv2 specialization (R4): occupancy round.
//  - 2 px/thread (tile 32x16) -> acc 32 regs -> 3 CTAs/SM (24 warps) to hide
//    LDS->FFMA latency that left issue at 56% in R3.
//  - tap specialization kept: center = direct load, edges = 1-D lerp,
//    corners = bilinear with shared horizontal row-lerps.

namespace {
constexpr int Hdim = 160;
constexpr int Wdim = 160;
constexpr int TILE_X = 32;
constexpr int TILE_Y = 16;
constexpr int HALO = 5;                     // shifts provably in [-4,4], +1 corner
constexpr int SMW  = TILE_X + 2 * HALO;     // 42
constexpr int SMH  = TILE_Y + 2 * HALO;     // 26
constexpr int THREADS = 256;
}

// Accumulate tap CK's 2 pixel samples into all 16 output accumulators.
#define EINSUM(CK, S0, S1) do {                                             \
    const float4* wr = reinterpret_cast<const float4*>(wsm[CK]);            \
    _Pragma("unroll")                                                       \
    for (int q = 0; q < 4; q++) {                                           \
        const float4 w = wr[q];                                             \
        acc[4*q+0][0] = fmaf(S0, w.x, acc[4*q+0][0]);                       \
        acc[4*q+0][1] = fmaf(S1, w.x, acc[4*q+0][1]);                       \
        acc[4*q+1][0] = fmaf(S0, w.y, acc[4*q+1][0]);                       \
        acc[4*q+1][1] = fmaf(S1, w.y, acc[4*q+1][1]);                       \
        acc[4*q+2][0] = fmaf(S0, w.z, acc[4*q+2][0]);                       \
        acc[4*q+2][1] = fmaf(S1, w.z, acc[4*q+2][1]);                       \
        acc[4*q+3][0] = fmaf(S0, w.w, acc[4*q+3][0]);                       \
        acc[4*q+3][1] = fmaf(S1, w.w, acc[4*q+3][1]);                       \
    }                                                                       \
} while (0)

__global__ __launch_bounds__(THREADS, 3)
void dcn_kernel(const float* __restrict__ input,
                const float* __restrict__ weight,
                const float* __restrict__ offset,
                float* __restrict__ out)
{
    const int bg = blockIdx.z;          // 0..47
    const int b  = bg / 3;
    const int g  = bg % 3;
    const int tile_x = blockIdx.x * TILE_X;
    const int tile_y = blockIdx.y * TILE_Y;

    __shared__ float sm[3][SMH][SMW];               // input tile + halo
    __shared__ __align__(16) float wsm[27][16];     // [c*9+k][o]

    const int tid = threadIdx.x;

    // ---- weights: w[g,o,c,k] = weight[k*144 + (g*16+o)*3 + c] ----
    for (int i = tid; i < 27 * 16; i += THREADS) {
        const int ck = i >> 4, o = i & 15;
        const int c = ck / 9, k = ck % 9;
        wsm[ck][o] = weight[k * 144 + (g * 16 + o) * 3 + c];
    }

    // ---- stage input tile (+halo, zero pad) ----
    const float* inb = input + (size_t)(b >> 1) * 9 * Hdim * Wdim
                             + (size_t)(g * 3) * Hdim * Wdim;
    for (int i = tid; i < 3 * SMH * SMW; i += THREADS) {
        const int c = i / (SMH * SMW);
        const int r = (i / SMW) % SMH;
        const int q = i % SMW;
        const int gy = tile_y + r - HALO;
        const int gx = tile_x + q - HALO;
        float v = 0.0f;
        if (gy >= 0 && gy < Hdim && gx >= 0 && gx < Wdim)
            v = inb[(size_t)c * Hdim * Wdim + gy * Wdim + gx];
        sm[c][r][q] = v;
    }

    // ---- shift constants (uniform across block) ----
    const float offy = __ldg(&offset[(b * 3 + g) * 2 + 0]);
    const float offx = __ldg(&offset[(b * 3 + g) * 2 + 1]);
    const float dyv = 1.0f + 3.0f / offy;   // shift magnitude for p_y = +-1
    const float dxv = 1.0f + 3.0f / offx;
    const float fyMf = floorf(-dyv), fyPf = floorf(dyv);
    const float fxMf = floorf(-dxv), fxPf = floorf(dxv);
    const int fyM = (int)fyMf, fyP = (int)fyPf;
    const int fxM = (int)fxMf, fxP = (int)fxPf;
    const float wyM = -dyv - fyMf, wyP = dyv - fyPf;
    const float wxM = -dxv - fxMf, wxP = dxv - fxPf;

    __syncthreads();

    // ---- compute: thread = 1 column x 2 contiguous rows ----
    const int tx = tid & 31;
    const int r0 = (tid >> 5) * 2;

    float acc[16][2];
    #pragma unroll
    for (int o = 0; o < 16; o++) {
        acc[o][0] = 0.0f;
        acc[o][1] = 0.0f;
    }

    #pragma unroll 1
    for (int c = 0; c < 3; c++) {
        const float* B  = &sm[c][r0 + HALO][tx + HALO];
        const float* BM = B + fyM * SMW;    // rows for p_y = -1
        const float* BP = B + fyP * SMW;    // rows for p_y = +1
        const int ckb = c * 9;

        // ===== p_y = 0 =====
        {   // k=4: center tap, direct loads
            EINSUM(ckb + 4, B[0], B[SMW]);
        }
        {   // k=3: horizontal lerp at fxM
            float t[2];
            #pragma unroll
            for (int p = 0; p < 2; p++) {
                float a = B[p * SMW + fxM], bb = B[p * SMW + fxM + 1];
                t[p] = fmaf(wxM, bb - a, a);
            }
            EINSUM(ckb + 3, t[0], t[1]);
        }
        {   // k=5: horizontal lerp at fxP
            float t[2];
            #pragma unroll
            for (int p = 0; p < 2; p++) {
                float a = B[p * SMW + fxP], bb = B[p * SMW + fxP + 1];
                t[p] = fmaf(wxP, bb - a, a);
            }
            EINSUM(ckb + 5, t[0], t[1]);
        }

        // ===== p_y = -1 (rows BM, weight wyM) =====
        {   // k=1: vertical-only lerp (col 0), 3 loads for 2 pixels
            float v0 = BM[0], v1 = BM[SMW], v2 = BM[2 * SMW];
            EINSUM(ckb + 1, fmaf(wyM, v1 - v0, v0), fmaf(wyM, v2 - v1, v1));
        }
        {   // k=0: bilinear; 3 shared horizontal lerps at fxM
            float h[3];
            #pragma unroll
            for (int j = 0; j < 3; j++) {
                float a = BM[j * SMW + fxM], bb = BM[j * SMW + fxM + 1];
                h[j] = fmaf(wxM, bb - a, a);
            }
            EINSUM(ckb + 0, fmaf(wyM, h[1] - h[0], h[0]), fmaf(wyM, h[2] - h[1], h[1]));
        }
        {   // k=2: bilinear at fxP
            float h[3];
            #pragma unroll
            for (int j = 0; j < 3; j++) {
                float a = BM[j * SMW + fxP], bb = BM[j * SMW + fxP + 1];
                h[j] = fmaf(wxP, bb - a, a);
            }
            EINSUM(ckb + 2, fmaf(wyM, h[1] - h[0], h[0]), fmaf(wyM, h[2] - h[1], h[1]));
        }

        // ===== p_y = +1 (rows BP, weight wyP) =====
        {   // k=7: vertical-only lerp
            float v0 = BP[0], v1 = BP[SMW], v2 = BP[2 * SMW];
            EINSUM(ckb + 7, fmaf(wyP, v1 - v0, v0), fmaf(wyP, v2 - v1, v1));
        }
        {   // k=6: bilinear at fxM
            float h[3];
            #pragma unroll
            for (int j = 0; j < 3; j++) {
                float a = BP[j * SMW + fxM], bb = BP[j * SMW + fxM + 1];
                h[j] = fmaf(wxM, bb - a, a);
            }
            EINSUM(ckb + 6, fmaf(wyP, h[1] - h[0], h[0]), fmaf(wyP, h[2] - h[1], h[1]));
        }
        {   // k=8: bilinear at fxP
            float h[3];
            #pragma unroll
            for (int j = 0; j < 3; j++) {
                float a = BP[j * SMW + fxP], bb = BP[j * SMW + fxP + 1];
                h[j] = fmaf(wxP, bb - a, a);
            }
            EINSUM(ckb + 8, fmaf(wyP, h[1] - h[0], h[0]), fmaf(wyP, h[2] - h[1], h[1]));
        }
    }

    // ---- store: out[b][g*16+o][y][x] ----
    float* outp = out + (size_t)(b * 48 + g * 16) * Hdim * Wdim
                      + (size_t)(tile_y + r0) * Wdim + tile_x + tx;
    #pragma unroll
    for (int o = 0; o < 16; o++) {
        outp[(size_t)o * (Hdim * Wdim)] = acc[o][0];
        outp[(size_t)o * (Hdim * Wdim) + Wdim] = acc[o][1];
    }
}

extern "C" void kernel_launch(void* const* d_in, const int* in_sizes, int n_in,
                              void* d_out, int out_size)
{
    const float* input  = (const float*)d_in[0];
    const float* weight = (const float*)d_in[1];
    const float* offset = (const float*)d_in[2];
    float* out = (float*)d_out;

    dim3 grid(Wdim / TILE_X, Hdim / TILE_Y, 48);   // 5 x 10 x 48
    dcn_kernel<<<grid, THREADS>>>(input, weight, offset, out);
}